// round 9
// baseline (speedup 1.0000x reference)
#include <cuda_runtime.h>
#include <cstdint>

#define SEQN 65536
#define HN   128
#define G4   512   // 4*H

typedef unsigned long long u64;

// Scratch (device globals: allocation-free per harness rules)
__device__ float g_GA[(size_t)SEQN * G4];   // precomputed x@WA1^T + bA1 + bA2
__device__ float g_HB[(size_t)SEQN * HN];   // hB per step, consumed by fc GEMM

// ---------------------------------------------------------------------------
// helpers
// ---------------------------------------------------------------------------
__device__ __forceinline__ float tanhfast(float x) {
    float y;
    asm("tanh.approx.f32 %0, %1;" : "=f"(y) : "f"(x));
    return y;
}
__device__ __forceinline__ float sigmfast(float x) {
    return fmaf(tanhfast(0.5f * x), 0.5f, 0.5f);
}

__device__ __forceinline__ uint32_t smem_u32(const void* p) {
    return (uint32_t)__cvta_generic_to_shared(p);
}
__device__ __forceinline__ uint32_t mapa_u32(uint32_t a, int rank) {
    uint32_t r;
    asm("mapa.shared::cluster.u32 %0, %1, %2;" : "=r"(r) : "r"(a), "r"(rank));
    return r;
}

#define MBAR_INIT(addr, cnt) \
    asm volatile("mbarrier.init.shared.b64 [%0], %1;" :: "r"(addr), "r"(cnt) : "memory")

#define MBAR_EXPECT_TX(addr, bytes) \
    asm volatile("mbarrier.arrive.expect_tx.shared.b64 _, [%0], %1;" \
                 :: "r"(addr), "r"(bytes) : "memory")

// local consumer wait (TMA-style): try_wait.parity.acquire.cta
__device__ __forceinline__ void wait_parity_cta(uint32_t mbar, uint32_t par) {
    asm volatile(
        "{\n\t.reg .pred P;\n\t"
        "WL_%=:\n\t"
        "mbarrier.try_wait.parity.acquire.cta.shared::cta.b64 P, [%0], %1, 0x989680;\n\t"
        "@P bra WD_%=;\n\t"
        "bra WL_%=;\n\t"
        "WD_%=:\n\t}"
        :: "r"(mbar), "r"(par) : "memory");
}

// bulk DSMEM copy: local SMEM -> remote SMEM, completes tx on remote mbarrier
#define BULK_CLUSTER(dst, src, bytes, mbar)                                          \
    asm volatile(                                                                    \
        "cp.async.bulk.shared::cluster.shared::cta.mbarrier::complete_tx::bytes "    \
        "[%0], [%1], %2, [%3];"                                                      \
        :: "r"(dst), "r"(src), "r"(bytes), "r"(mbar) : "memory")

#define FENCE_PROXY_ASYNC() asm volatile("fence.proxy.async.shared::cta;" ::: "memory")

#define FMA2(acc, w, h) \
    asm("fma.rn.f32x2 %0, %1, %2, %0;" : "+l"(acc) : "l"(w), "l"(h))

#define CLUSTER_SYNC_()                                                        \
    do {                                                                       \
        asm volatile("barrier.cluster.arrive.aligned;" ::: "memory");          \
        asm volatile("barrier.cluster.wait.aligned;"   ::: "memory");          \
    } while (0)

// ---------------------------------------------------------------------------
// Kernel 1: GA[t, 512] = x[t] @ WA1^T + bA1 + bA2
// ---------------------------------------------------------------------------
__global__ void __launch_bounds__(128) ga_kernel(const float* __restrict__ x,
                                                 const float* __restrict__ W,
                                                 const float* __restrict__ b1,
                                                 const float* __restrict__ b2) {
    __shared__ float xs[64 * 128];
    const int tid = threadIdx.x;
    const int row = (blockIdx.y << 7) + tid;

    float4 w[32];
    const float4* wg = (const float4*)(W + (size_t)row * 128);
#pragma unroll
    for (int k = 0; k < 32; k++) w[k] = wg[k];
    const float bias = b1[row] + b2[row];

    const int t0 = blockIdx.x * 64;
    const float4* xg = (const float4*)(x + (size_t)t0 * 128);
    float4* xs4 = (float4*)xs;
#pragma unroll
    for (int i = 0; i < 16; i++) xs4[tid + (i << 7)] = xg[tid + (i << 7)];
    __syncthreads();

    for (int tt = 0; tt < 64; tt++) {
        const float4* hx = (const float4*)(xs + tt * 128);
        float a0 = 0.f, a1 = 0.f, a2 = 0.f, a3 = 0.f;
#pragma unroll
        for (int k = 0; k < 32; k++) {
            float4 h = hx[k];
            a0 = fmaf(w[k].x, h.x, a0);
            a1 = fmaf(w[k].y, h.y, a1);
            a2 = fmaf(w[k].z, h.z, a2);
            a3 = fmaf(w[k].w, h.w, a3);
        }
        g_GA[(size_t)(t0 + tt) * G4 + row] = (a0 + a1) + (a2 + a3) + bias;
    }
}

// ---------------------------------------------------------------------------
// Kernel 2: recurrence with HW producer-consumer sync (NO barrier.cluster in
// the loop). 8-CTA cluster, 384 threads, B one tick behind A (R2 schedule).
//
// Incoming h buffer s_in[buf][8 groups x 32] : group g = {hA[16g..+16), hB[...]}
// from rank g, delivered by rank g's cp.async.bulk (128B) which complete_tx's
// this CTA's mbarrier bar[buf]. Consumer: local try_wait.parity.acquire.cta.
// expect_tx(1024B) armed 2 ticks ahead (happens-before proven via own bulk
// completion chain). Phases tracked per-barrier in registers.
// ---------------------------------------------------------------------------
__global__ void __cluster_dims__(8, 1, 1) __launch_bounds__(384, 1)
recur_kernel(const float* __restrict__ WA2, const float* __restrict__ WB1,
             const float* __restrict__ WB2, const float* __restrict__ bB1,
             const float* __restrict__ bB2, const float* __restrict__ hA0,
             const float* __restrict__ cA0, const float* __restrict__ hB0,
             const float* __restrict__ cB0, float* __restrict__ out,
             int write_states) {
    __shared__ alignas(16) float s_in[2][256];   // incoming h, grouped by src CTA
    __shared__ alignas(16) float s_stage[32];    // outgoing {16 hA, 16 hB}
    __shared__ float s_uA[64];   // WA2 dots (+GA)
    __shared__ float s_wB[64];   // WB1 dots
    __shared__ float s_vB[64];   // WB2 dots
    __shared__ float s_bb[64];   // bB1+bB2
    __shared__ alignas(8) u64 s_bar[2];

    const int c    = blockIdx.x;
    const int tid  = threadIdx.x;
    const int rs   = tid >> 1;      // 0..191
    const int half = tid & 1;
    const int mat  = rs >> 6;       // 0:WA2 1:WB1 2:WB2
    const int r    = rs & 63;
    const int grow = ((r >> 4) << 7) + (c << 4) + (r & 15);

    // ---- weights as packed f32x2 ----
    const float* Wp = (mat == 0) ? WA2 : (mat == 1) ? WB1 : WB2;
    u64 wv[32];
    {
        const ulonglong2* wg = (const ulonglong2*)(Wp + (size_t)grow * 128 + half * 64);
#pragma unroll
        for (int k = 0; k < 16; k++) { ulonglong2 q = wg[k]; wv[2*k] = q.x; wv[2*k+1] = q.y; }
    }

    // ---- init SMEM ----
    if (tid < 64) {
        const int gr = ((tid >> 4) << 7) + (c << 4) + (tid & 15);
        s_bb[tid] = bB1[gr] + bB2[gr];
    }
    if (tid < HN) {
        const int g = tid >> 4, i = tid & 15;
        s_in[0][g * 32 + i]      = hA0[tid];  // hA(-1), read at tick 0
        s_in[0][g * 32 + 16 + i] = 0.f;       // hB slots: dots discarded at tick 0
    }
    const uint32_t bloc0 = smem_u32(&s_bar[0]);
    const uint32_t bloc1 = smem_u32(&s_bar[1]);
    if (tid == 0) {
        MBAR_INIT(bloc0, 1);
        MBAR_INIT(bloc1, 1);
        MBAR_EXPECT_TX(bloc1, 1024);   // arm tick 1 (buf 1)
        MBAR_EXPECT_TX(bloc0, 1024);   // arm tick 2 (buf 0)
    }
    const bool isA = (tid < 16);
    const bool isB = (tid >= 32 && tid < 48);
    float cAr = 0.f, cBr = 0.f, hB_init = 0.f;
    if (isA) cAr = cA0[(c << 4) + tid];
    if (isB) { cBr = cB0[(c << 4) + (tid - 32)]; hB_init = hB0[(c << 4) + (tid - 32)]; }
    __syncthreads();
    CLUSTER_SYNC_();   // all CTAs' SMEM + armed barriers visible before any bulk

    const uint32_t stage_a = smem_u32(s_stage);
    const uint32_t in_a[2] = { smem_u32(&s_in[0][c * 32]), smem_u32(&s_in[1][c * 32]) };

    // ---- GA prefetch, distance 2 (mat==0 half==0 lanes) ----
    const bool is_ga = (mat == 0) && (half == 0);
    float ga0 = 0.f, ga1 = 0.f;
    if (is_ga) {
        ga0 = g_GA[grow];
        ga1 = __ldg(&g_GA[(size_t)G4 + grow]);
    }

    const size_t OH = (size_t)SEQN * HN;
    uint32_t ph0 = 0, ph1 = 0;   // phase parity per barrier

    for (int t = 0; t <= SEQN; t++) {
        const int pb = t & 1;

        // ===== wait for this tick's h delivery (local, HW-signaled) =====
        if (t > 0) {
            if (pb) { wait_parity_cta(bloc1, ph1); ph1 ^= 1; }
            else    { wait_parity_cta(bloc0, ph0); ph0 ^= 1; }
            // re-arm this barrier for tick t+2 (before syncthreads / stores)
            if (tid == 0 && t + 2 <= SEQN)
                MBAR_EXPECT_TX(pb ? bloc1 : bloc0, 1024);
        }

        float ga2 = 0.f;
        if (is_ga && t + 2 < SEQN)
            ga2 = __ldg(&g_GA[(size_t)(t + 2) * G4 + grow]);

        // ===== merged matvec (FFMA2) over grouped s_in layout =====
        {
            const float* hb = s_in[pb] + ((mat == 2) ? 16 : 0);
            u64 a0 = 0ULL, a1 = 0ULL;
#pragma unroll
            for (int gi = 0; gi < 4; gi++) {
                const ulonglong2* hv =
                    (const ulonglong2*)(hb + (4 * half + gi) * 32);
#pragma unroll
                for (int j = 0; j < 4; j++) {
                    ulonglong2 h2 = hv[j];
                    FMA2(a0, wv[gi * 8 + 2 * j],     h2.x);
                    FMA2(a1, wv[gi * 8 + 2 * j + 1], h2.y);
                }
            }
            float2 f0 = *(float2*)&a0, f1 = *(float2*)&a1;
            float s = (f0.x + f0.y) + (f1.x + f1.y);
            s += __shfl_down_sync(0xffffffffu, s, 1);
            if (half == 0) {
                if (mat == 0)      s_uA[r] = s + ga0;
                else if (mat == 1) s_wB[r] = s;
                else               s_vB[r] = s;
            }
        }
        __syncthreads();

        // ===== cell A activation (step t), warp 0 lanes 0-15 =====
        if (isA && t < SEQN) {
            const float gi = s_uA[tid];
            const float gf = s_uA[16 + tid];
            const float gg = s_uA[32 + tid];
            const float go = s_uA[48 + tid];
            const float cn = sigmfast(gf) * cAr + sigmfast(gi) * tanhfast(gg);
            cAr = cn;
            const float h = sigmfast(go) * tanhfast(cn);
            s_stage[tid] = h;
            if (write_states && t == SEQN - 1) {
                const int j = (c << 4) + tid;
                out[OH + j]      = h;
                out[OH + HN + j] = cn;
            }
        }

        // ===== cell B activation (step t-1), warp 1 lanes 0-15 =====
        if (isB) {
            const int ln = tid - 32;
            float h, cn = cBr;
            if (t == 0) {
                h = hB_init;
            } else {
                const float gi = s_wB[ln]      + s_vB[ln]      + s_bb[ln];
                const float gf = s_wB[16 + ln] + s_vB[16 + ln] + s_bb[16 + ln];
                const float gg = s_wB[32 + ln] + s_vB[32 + ln] + s_bb[32 + ln];
                const float go = s_wB[48 + ln] + s_vB[48 + ln] + s_bb[48 + ln];
                cn = sigmfast(gf) * cBr + sigmfast(gi) * tanhfast(gg);
                cBr = cn;
                h = sigmfast(go) * tanhfast(cn);
            }
            s_stage[16 + ln] = h;
            if (t >= 1) {
                const int j = (c << 4) + ln;
                g_HB[(size_t)(t - 1) * HN + j] = h;
                if (write_states && t == SEQN) {
                    out[OH + 2 * HN + j] = h;
                    out[OH + 3 * HN + j] = cn;
                }
            }
        }

        // ===== publish: 8 bulk copies (128B each) deliver h + completion =====
        if (t < SEQN && tid < 64) {
            asm volatile("bar.sync 1, 64;" ::: "memory");   // warps 0-1: stage ready
            if (tid == 16) {                                 // idle lane issues
                FENCE_PROXY_ASYNC();
                const int nb = pb ^ 1;
                const uint32_t dl = in_a[nb];
                const uint32_t bl = nb ? bloc1 : bloc0;
#pragma unroll
                for (int rk = 0; rk < 8; rk++) {
                    const uint32_t dst = mapa_u32(dl, rk);
                    const uint32_t mb  = mapa_u32(bl, rk);
                    BULK_CLUSTER(dst, stage_a, 128u, mb);
                }
            }
        }

        if (is_ga) { ga0 = ga1; ga1 = ga2; }
    }

    CLUSTER_SYNC_();   // keep peers' SMEM alive until all remote traffic done
}

// ---------------------------------------------------------------------------
// Kernel 3: logits[t] = hB[t] @ Wfc^T + bfc
// ---------------------------------------------------------------------------
__global__ void __launch_bounds__(128) fc_kernel(const float* __restrict__ W,
                                                 const float* __restrict__ b,
                                                 float* __restrict__ out) {
    __shared__ float hs[64 * 128];
    const int tid = threadIdx.x;

    float4 w[32];
    const float4* wg = (const float4*)(W + (size_t)tid * 128);
#pragma unroll
    for (int k = 0; k < 32; k++) w[k] = wg[k];
    const float bias = b[tid];

    const int t0 = blockIdx.x * 64;
    const float4* hg = (const float4*)(g_HB + (size_t)t0 * 128);
    float4* hs4 = (float4*)hs;
#pragma unroll
    for (int i = 0; i < 16; i++) hs4[tid + (i << 7)] = hg[tid + (i << 7)];
    __syncthreads();

    for (int tt = 0; tt < 64; tt++) {
        const float4* hx = (const float4*)(hs + tt * 128);
        float a0 = 0.f, a1 = 0.f, a2 = 0.f, a3 = 0.f;
#pragma unroll
        for (int k = 0; k < 32; k++) {
            float4 h = hx[k];
            a0 = fmaf(w[k].x, h.x, a0);
            a1 = fmaf(w[k].y, h.y, a1);
            a2 = fmaf(w[k].z, h.z, a2);
            a3 = fmaf(w[k].w, h.w, a3);
        }
        out[(size_t)(t0 + tt) * 128 + tid] = (a0 + a1) + (a2 + a3) + bias;
    }
}

// ---------------------------------------------------------------------------
// launch
// inputs: 0 x, 1 hA, 2 cA, 3 hB, 4 cB, 5 WA1, 6 bA1, 7 WA2, 8 bA2,
//         9 WB1, 10 bB1, 11 WB2, 12 bB2, 13 Wfc, 14 bfc
// ---------------------------------------------------------------------------
extern "C" void kernel_launch(void* const* d_in, const int* in_sizes, int n_in,
                              void* d_out, int out_size) {
    const float* x   = (const float*)d_in[0];
    const float* hA0 = (const float*)d_in[1];
    const float* cA0 = (const float*)d_in[2];
    const float* hB0 = (const float*)d_in[3];
    const float* cB0 = (const float*)d_in[4];
    const float* WA1 = (const float*)d_in[5];
    const float* bA1 = (const float*)d_in[6];
    const float* WA2 = (const float*)d_in[7];
    const float* bA2 = (const float*)d_in[8];
    const float* WB1 = (const float*)d_in[9];
    const float* bB1 = (const float*)d_in[10];
    const float* WB2 = (const float*)d_in[11];
    const float* bB2 = (const float*)d_in[12];
    const float* Wfc = (const float*)d_in[13];
    const float* bfc = (const float*)d_in[14];
    float* out = (float*)d_out;

    const int write_states = (out_size >= SEQN * HN + 4 * HN) ? 1 : 0;

    ga_kernel<<<dim3(SEQN / 64, 4), 128>>>(x, WA1, bA1, bA2);
    recur_kernel<<<8, 384>>>(WA2, WB1, WB2, bB1, bB2, hA0, cA0, hB0, cB0, out,
                             write_states);
    fc_kernel<<<SEQN / 64, 128>>>(Wfc, bfc, out);
}

// round 10
// speedup vs baseline: 1.1045x; 1.1045x over previous
#include <cuda_runtime.h>
#include <cstdint>

#define SEQN 65536
#define HN   128
#define G4   512   // 4*H

typedef unsigned long long u64;

// Scratch (device globals: allocation-free per harness rules)
__device__ float g_GA[(size_t)SEQN * G4];   // x@WA1^T + bA1 + bA2
__device__ float g_HB[(size_t)SEQN * HN];   // hB per step (fc input)
__device__ u64   g_msg[(size_t)SEQN * HN];  // {hA:f32(lo), tick:u32(hi)} A->B bridge

// ---------------------------------------------------------------------------
// helpers
// ---------------------------------------------------------------------------
__device__ __forceinline__ float tanhfast(float x) {
    float y;
    asm("tanh.approx.f32 %0, %1;" : "=f"(y) : "f"(x));
    return y;
}
__device__ __forceinline__ float sigmfast(float x) {
    return fmaf(tanhfast(0.5f * x), 0.5f, 0.5f);
}

__device__ __forceinline__ void st_remote_f32(float* p, int rank, float v) {
    uint32_t addr = (uint32_t)__cvta_generic_to_shared(p);
    uint32_t raddr;
    asm volatile("mapa.shared::cluster.u32 %0, %1, %2;" : "=r"(raddr) : "r"(addr), "r"(rank));
    asm volatile("st.shared::cluster.f32 [%0], %1;" :: "r"(raddr), "f"(v) : "memory");
}

#define FMA2(acc, w, h) \
    asm("fma.rn.f32x2 %0, %1, %2, %0;" : "+l"(acc) : "l"(w), "l"(h))

#define CLUSTER_ARRIVE_() asm volatile("barrier.cluster.arrive.aligned;" ::: "memory")
#define CLUSTER_WAIT_()   asm volatile("barrier.cluster.wait.aligned;"   ::: "memory")
#define CLUSTER_SYNC_()   do { CLUSTER_ARRIVE_(); CLUSTER_WAIT_(); } while (0)

// ---------------------------------------------------------------------------
// Kernel 0: reset the A->B message tags (race-free across graph replays)
// ---------------------------------------------------------------------------
__global__ void __launch_bounds__(256) reset_kernel() {
    const size_t N = (size_t)SEQN * HN;
    size_t i = (size_t)blockIdx.x * blockDim.x + threadIdx.x;
    const size_t stride = (size_t)gridDim.x * blockDim.x;
    for (; i < N; i += stride) g_msg[i] = 0xFFFFFFFF00000000ULL;  // tag = -1
}

// ---------------------------------------------------------------------------
// Kernel 1: GA[t, 512] = x[t] @ WA1^T + bA1 + bA2
// ---------------------------------------------------------------------------
__global__ void __launch_bounds__(128) ga_kernel(const float* __restrict__ x,
                                                 const float* __restrict__ W,
                                                 const float* __restrict__ b1,
                                                 const float* __restrict__ b2) {
    __shared__ float xs[64 * 128];
    const int tid = threadIdx.x;
    const int row = (blockIdx.y << 7) + tid;

    float4 w[32];
    const float4* wg = (const float4*)(W + (size_t)row * 128);
#pragma unroll
    for (int k = 0; k < 32; k++) w[k] = wg[k];
    const float bias = b1[row] + b2[row];

    const int t0 = blockIdx.x * 64;
    const float4* xg = (const float4*)(x + (size_t)t0 * 128);
    float4* xs4 = (float4*)xs;
#pragma unroll
    for (int i = 0; i < 16; i++) xs4[tid + (i << 7)] = xg[tid + (i << 7)];
    __syncthreads();

    for (int tt = 0; tt < 64; tt++) {
        const float4* hx = (const float4*)(xs + tt * 128);
        float a0 = 0.f, a1 = 0.f, a2 = 0.f, a3 = 0.f;
#pragma unroll
        for (int k = 0; k < 32; k++) {
            float4 h = hx[k];
            a0 = fmaf(w[k].x, h.x, a0);
            a1 = fmaf(w[k].y, h.y, a1);
            a2 = fmaf(w[k].z, h.z, a2);
            a3 = fmaf(w[k].w, h.w, a3);
        }
        g_GA[(size_t)(t0 + tt) * G4 + row] = (a0 + a1) + (a2 + a3) + bias;
    }
}

// ---------------------------------------------------------------------------
// Kernel 2: split-chain recurrence, TWO 4-CTA clusters (grid=8, cluster=4).
//   Blocks 0-3  (cluster 0) = chain A: hA(t) = lstmA(hA(t-1); GA(t)).
//     256 matvec threads (128 WA2 rows/CTA, halves), warp0 does 32 cells' act,
//     4-way DSMEM broadcast, publishes {hA,t} via 8B volatile GMEM store.
//   Blocks 4-7  (cluster 1) = chain B: hB(t) = lstmB(hB(t-1); hA(t)).
//     512 matvec threads (128 WB1 + 128 WB2 rows/CTA, halves), 64 spinner
//     threads stage hA(t+1) from L2 during tick t (hidden once A leads),
//     warp0 act, 4-way broadcast.
// Each cluster syncs only itself with barrier.cluster (4 arrivals, same-die).
// ---------------------------------------------------------------------------
__global__ void __cluster_dims__(4, 1, 1) __launch_bounds__(576, 1)
recur_kernel(const float* __restrict__ WA2, const float* __restrict__ WB1,
             const float* __restrict__ WB2, const float* __restrict__ bB1,
             const float* __restrict__ bB2, const float* __restrict__ hA0,
             const float* __restrict__ cA0, const float* __restrict__ hB0,
             const float* __restrict__ cB0, float* __restrict__ out,
             int write_states) {
    __shared__ alignas(16) float s_h[2][HN];    // A: hA bufs | B: hB bufs
    __shared__ alignas(16) float s_hX[2][HN];   // B only: staged hA
    __shared__ float s_d0[HN];                  // A: dots(+GA) | B: WB1 dots
    __shared__ float s_d1[HN];                  // B: WB2 dots
    __shared__ float s_bb[HN];                  // B: bB1+bB2

    const int c    = blockIdx.x & 3;            // rank within cluster
    const int tid  = threadIdx.x;
    const int lane = tid & 31;
    const size_t OH = (size_t)SEQN * HN;

    if (blockIdx.x < 4) {
        // ==================== ROLE A: hA chain ====================
        const int row  = tid >> 1;    // 0..127 (valid tid<256): gate*32 + jloc
        const int half = tid & 1;
        const int grow = ((row >> 5) << 7) + (c << 5) + (row & 31);

        u64 wv[32];
        if (tid < 256) {
            const ulonglong2* wg =
                (const ulonglong2*)(WA2 + (size_t)grow * 128 + half * 64);
#pragma unroll
            for (int k = 0; k < 16; k++) { ulonglong2 q = wg[k]; wv[2*k] = q.x; wv[2*k+1] = q.y; }
        }
        if (tid < HN) s_h[0][tid] = hA0[tid];
        float cAr = 0.f;
        if (tid < 32) cAr = cA0[(c << 5) + lane];

        __syncthreads();
        CLUSTER_SYNC_();

        const bool is_ga = (tid < 256) && (half == 0);
        float ga0 = 0.f, ga1 = 0.f;
        if (is_ga) {
            ga0 = g_GA[grow];
            ga1 = __ldg(&g_GA[(size_t)G4 + grow]);
        }

        for (int t = 0; t < SEQN; t++) {
            const int pb = t & 1;
            float ga2 = 0.f;
            if (is_ga && t + 2 < SEQN)
                ga2 = __ldg(&g_GA[(size_t)(t + 2) * G4 + grow]);

            if (tid < 256) {
                const ulonglong2* hv = (const ulonglong2*)(s_h[pb] + half * 64);
                u64 a0 = 0ULL, a1 = 0ULL;
#pragma unroll
                for (int k = 0; k < 16; k++) {
                    ulonglong2 h2 = hv[k];
                    FMA2(a0, wv[2*k],     h2.x);
                    FMA2(a1, wv[2*k + 1], h2.y);
                }
                float2 f0 = *(float2*)&a0, f1 = *(float2*)&a1;
                float s = (f0.x + f0.y) + (f1.x + f1.y);
                s += __shfl_down_sync(0xffffffffu, s, 1);
                if (half == 0) s_d0[row] = s + ga0;
            }
            __syncthreads();

            if (tid < 32) {
                const float gi = s_d0[lane];
                const float gf = s_d0[32 + lane];
                const float gg = s_d0[64 + lane];
                const float go = s_d0[96 + lane];
                const float cn = sigmfast(gf) * cAr + sigmfast(gi) * tanhfast(gg);
                cAr = cn;
                const float h = sigmfast(go) * tanhfast(cn);
                const int j = (c << 5) + lane;
#pragma unroll
                for (int rk = 0; rk < 4; rk++) st_remote_f32(&s_h[pb ^ 1][j], rk, h);
                // publish {h, t} to chain B (single aligned 8B store)
                const u64 m = (u64)__float_as_uint(h) | ((u64)(uint32_t)t << 32);
                *((volatile u64*)&g_msg[(size_t)t * HN + j]) = m;
                if (write_states && t == SEQN - 1) {
                    out[OH + j]      = h;
                    out[OH + HN + j] = cn;
                }
            }
            CLUSTER_ARRIVE_();
            if (is_ga) { ga0 = ga1; ga1 = ga2; }
            CLUSTER_WAIT_();
        }
        CLUSTER_SYNC_();
    } else {
        // ==================== ROLE B: hB chain ====================
        const int rs   = tid >> 1;    // 0..255 (valid tid<512)
        const int half = tid & 1;
        const int mat  = rs >> 7;     // 0: WB1 (reads hA), 1: WB2 (reads hB)
        const int row  = rs & 127;    // gate*32 + jloc
        const int grow = ((row >> 5) << 7) + (c << 5) + (row & 31);

        u64 wv[32];
        if (tid < 512) {
            const float* Wp = mat ? WB2 : WB1;
            const ulonglong2* wg =
                (const ulonglong2*)(Wp + (size_t)grow * 128 + half * 64);
#pragma unroll
            for (int k = 0; k < 16; k++) { ulonglong2 q = wg[k]; wv[2*k] = q.x; wv[2*k+1] = q.y; }
        }
        if (tid < HN) {
            const int gr = ((tid >> 5) << 7) + (c << 5) + (tid & 31);
            s_bb[tid] = bB1[gr] + bB2[gr];
            s_h[0][tid] = hB0[tid];
        }
        float cBr = 0.f;
        if (tid < 32) cBr = cB0[(c << 5) + lane];

        __syncthreads();
        CLUSTER_SYNC_();

        // pre-stage hA(0): spinner threads (tid 512..575), 2 slots each
        if (tid >= 512) {
            const int s0 = (tid - 512) << 1;
#pragma unroll
            for (int k = 0; k < 2; k++) {
                u64 v;
                do { v = *((volatile u64*)&g_msg[s0 + k]); }
                while ((uint32_t)(v >> 32) != 0u);
                s_hX[0][s0 + k] = __uint_as_float((uint32_t)v);
            }
        }
        __syncthreads();

        for (int t = 0; t < SEQN; t++) {
            const int pb = t & 1;

            if (tid < 512) {
                const float* hsrc = mat ? s_h[pb] : s_hX[pb];
                const ulonglong2* hv = (const ulonglong2*)(hsrc + half * 64);
                u64 a0 = 0ULL, a1 = 0ULL;
#pragma unroll
                for (int k = 0; k < 16; k++) {
                    ulonglong2 h2 = hv[k];
                    FMA2(a0, wv[2*k],     h2.x);
                    FMA2(a1, wv[2*k + 1], h2.y);
                }
                float2 f0 = *(float2*)&a0, f1 = *(float2*)&a1;
                float s = (f0.x + f0.y) + (f1.x + f1.y);
                s += __shfl_down_sync(0xffffffffu, s, 1);
                if (half == 0) {
                    if (mat == 0) s_d0[row] = s;
                    else          s_d1[row] = s;
                }
            } else if (t + 1 < SEQN) {
                // stage hA(t+1) concurrently with this tick's matvec
                const int s0 = (tid - 512) << 1;
                const uint32_t want = (uint32_t)(t + 1);
                const size_t base = (size_t)(t + 1) * HN;
#pragma unroll
                for (int k = 0; k < 2; k++) {
                    u64 v;
                    do { v = *((volatile u64*)&g_msg[base + s0 + k]); }
                    while ((uint32_t)(v >> 32) != want);
                    s_hX[pb ^ 1][s0 + k] = __uint_as_float((uint32_t)v);
                }
            }
            __syncthreads();

            if (tid < 32) {
                const float gi = s_d0[lane]      + s_d1[lane]      + s_bb[lane];
                const float gf = s_d0[32 + lane] + s_d1[32 + lane] + s_bb[32 + lane];
                const float gg = s_d0[64 + lane] + s_d1[64 + lane] + s_bb[64 + lane];
                const float go = s_d0[96 + lane] + s_d1[96 + lane] + s_bb[96 + lane];
                const float cn = sigmfast(gf) * cBr + sigmfast(gi) * tanhfast(gg);
                cBr = cn;
                const float h = sigmfast(go) * tanhfast(cn);
                const int j = (c << 5) + lane;
#pragma unroll
                for (int rk = 0; rk < 4; rk++) st_remote_f32(&s_h[pb ^ 1][j], rk, h);
                g_HB[(size_t)t * HN + j] = h;
                if (write_states && t == SEQN - 1) {
                    out[OH + 2 * HN + j] = h;
                    out[OH + 3 * HN + j] = cn;
                }
            }
            CLUSTER_ARRIVE_();
            CLUSTER_WAIT_();
        }
        CLUSTER_SYNC_();
    }
}

// ---------------------------------------------------------------------------
// Kernel 3: logits[t] = hB[t] @ Wfc^T + bfc
// ---------------------------------------------------------------------------
__global__ void __launch_bounds__(128) fc_kernel(const float* __restrict__ W,
                                                 const float* __restrict__ b,
                                                 float* __restrict__ out) {
    __shared__ float hs[64 * 128];
    const int tid = threadIdx.x;

    float4 w[32];
    const float4* wg = (const float4*)(W + (size_t)tid * 128);
#pragma unroll
    for (int k = 0; k < 32; k++) w[k] = wg[k];
    const float bias = b[tid];

    const int t0 = blockIdx.x * 64;
    const float4* hg = (const float4*)(g_HB + (size_t)t0 * 128);
    float4* hs4 = (float4*)hs;
#pragma unroll
    for (int i = 0; i < 16; i++) hs4[tid + (i << 7)] = hg[tid + (i << 7)];
    __syncthreads();

    for (int tt = 0; tt < 64; tt++) {
        const float4* hx = (const float4*)(hs + tt * 128);
        float a0 = 0.f, a1 = 0.f, a2 = 0.f, a3 = 0.f;
#pragma unroll
        for (int k = 0; k < 32; k++) {
            float4 h = hx[k];
            a0 = fmaf(w[k].x, h.x, a0);
            a1 = fmaf(w[k].y, h.y, a1);
            a2 = fmaf(w[k].z, h.z, a2);
            a3 = fmaf(w[k].w, h.w, a3);
        }
        out[(size_t)(t0 + tt) * 128 + tid] = (a0 + a1) + (a2 + a3) + bias;
    }
}

// ---------------------------------------------------------------------------
// launch
// ---------------------------------------------------------------------------
extern "C" void kernel_launch(void* const* d_in, const int* in_sizes, int n_in,
                              void* d_out, int out_size) {
    const float* x   = (const float*)d_in[0];
    const float* hA0 = (const float*)d_in[1];
    const float* cA0 = (const float*)d_in[2];
    const float* hB0 = (const float*)d_in[3];
    const float* cB0 = (const float*)d_in[4];
    const float* WA1 = (const float*)d_in[5];
    const float* bA1 = (const float*)d_in[6];
    const float* WA2 = (const float*)d_in[7];
    const float* bA2 = (const float*)d_in[8];
    const float* WB1 = (const float*)d_in[9];
    const float* bB1 = (const float*)d_in[10];
    const float* WB2 = (const float*)d_in[11];
    const float* bB2 = (const float*)d_in[12];
    const float* Wfc = (const float*)d_in[13];
    const float* bfc = (const float*)d_in[14];
    float* out = (float*)d_out;

    const int write_states = (out_size >= SEQN * HN + 4 * HN) ? 1 : 0;

    ga_kernel<<<dim3(SEQN / 64, 4), 128>>>(x, WA1, bA1, bA2);
    reset_kernel<<<2048, 256>>>();
    recur_kernel<<<8, 576>>>(WA2, WB1, WB2, bB1, bB2, hA0, cA0, hB0, cB0, out,
                             write_states);
    fc_kernel<<<SEQN / 64, 128>>>(Wfc, bfc, out);
}

// round 11
// speedup vs baseline: 1.2874x; 1.1656x over previous
#include <cuda_runtime.h>
#include <cstdint>

#define SEQN 65536
#define HN   128
#define G4   512   // 4*H

typedef unsigned long long u64;

// Scratch (device globals: allocation-free per harness rules)
__device__ float g_GA[(size_t)SEQN * G4];   // precomputed x@WA1^T + bA1 + bA2
__device__ float g_HB[(size_t)SEQN * HN];   // hB per step, consumed by fc GEMM

// ---------------------------------------------------------------------------
// helpers
// ---------------------------------------------------------------------------
__device__ __forceinline__ float tanhfast(float x) {
    float y;
    asm("tanh.approx.f32 %0, %1;" : "=f"(y) : "f"(x));
    return y;
}
__device__ __forceinline__ float sigmfast(float x) {
    return fmaf(tanhfast(0.5f * x), 0.5f, 0.5f);
}

__device__ __forceinline__ uint32_t smem_u32(const void* p) {
    return (uint32_t)__cvta_generic_to_shared(p);
}
__device__ __forceinline__ uint32_t mapa_u32(uint32_t a, int rank) {
    uint32_t r;
    asm("mapa.shared::cluster.u32 %0, %1, %2;" : "=r"(r) : "r"(a), "r"(rank));
    return r;
}

// one 16-byte vector store into a peer CTA's SMEM
__device__ __forceinline__ void st_cluster_v4(uint32_t addr, float4 v) {
    asm volatile("st.shared::cluster.v4.f32 [%0], {%1, %2, %3, %4};"
                 :: "r"(addr), "f"(v.x), "f"(v.y), "f"(v.z), "f"(v.w) : "memory");
}

#define FMA2(acc, w, h) \
    asm("fma.rn.f32x2 %0, %1, %2, %0;" : "+l"(acc) : "l"(w), "l"(h))

#define CLUSTER_ARRIVE_() asm volatile("barrier.cluster.arrive.aligned;" ::: "memory")
#define CLUSTER_WAIT_()   asm volatile("barrier.cluster.wait.aligned;"   ::: "memory")
#define CLUSTER_SYNC_()   do { CLUSTER_ARRIVE_(); CLUSTER_WAIT_(); } while (0)

// ---------------------------------------------------------------------------
// Kernel 1: GA[t, 512] = x[t] @ WA1^T + bA1 + bA2
// ---------------------------------------------------------------------------
__global__ void __launch_bounds__(128) ga_kernel(const float* __restrict__ x,
                                                 const float* __restrict__ W,
                                                 const float* __restrict__ b1,
                                                 const float* __restrict__ b2) {
    __shared__ float xs[64 * 128];
    const int tid = threadIdx.x;
    const int row = (blockIdx.y << 7) + tid;

    float4 w[32];
    const float4* wg = (const float4*)(W + (size_t)row * 128);
#pragma unroll
    for (int k = 0; k < 32; k++) w[k] = wg[k];
    const float bias = b1[row] + b2[row];

    const int t0 = blockIdx.x * 64;
    const float4* xg = (const float4*)(x + (size_t)t0 * 128);
    float4* xs4 = (float4*)xs;
#pragma unroll
    for (int i = 0; i < 16; i++) xs4[tid + (i << 7)] = xg[tid + (i << 7)];
    __syncthreads();

    for (int tt = 0; tt < 64; tt++) {
        const float4* hx = (const float4*)(xs + tt * 128);
        float a0 = 0.f, a1 = 0.f, a2 = 0.f, a3 = 0.f;
#pragma unroll
        for (int k = 0; k < 32; k++) {
            float4 h = hx[k];
            a0 = fmaf(w[k].x, h.x, a0);
            a1 = fmaf(w[k].y, h.y, a1);
            a2 = fmaf(w[k].z, h.z, a2);
            a3 = fmaf(w[k].w, h.w, a3);
        }
        g_GA[(size_t)(t0 + tt) * G4 + row] = (a0 + a1) + (a2 + a3) + bias;
    }
}

// ---------------------------------------------------------------------------
// Kernel 2: R8 champion + VECTORIZED broadcast (ingress-packet hypothesis).
// 8-CTA cluster, 384 threads, B one tick behind A.
// Incoming h buffer s_in[buf][rank*32]: {16 hA, 16 hB} per source rank.
// Per tick: matvec (FFMA2, grouped layout) -> syncthreads -> acts (warp0 A,
// warp1 B) write s_stage[32] locally -> bar.sync(1,64) -> 64 lanes issue ONE
// st.shared::cluster.v4 each (rank = lane>>3, chunk = lane&7) -> arrive ->
// GMEM side-writes + GA rotate -> wait. Ingress/CTA: 64 packets vs 256.
// ---------------------------------------------------------------------------
__global__ void __cluster_dims__(8, 1, 1) __launch_bounds__(384, 1)
recur_kernel(const float* __restrict__ WA2, const float* __restrict__ WB1,
             const float* __restrict__ WB2, const float* __restrict__ bB1,
             const float* __restrict__ bB2, const float* __restrict__ hA0,
             const float* __restrict__ cA0, const float* __restrict__ hB0,
             const float* __restrict__ cB0, float* __restrict__ out,
             int write_states) {
    __shared__ alignas(16) float s_in[2][256];   // grouped: rank g -> [32g..32g+32)
    __shared__ alignas(16) float s_stage[32];    // {16 hA, 16 hB} outgoing
    __shared__ float s_uA[64];   // WA2 dots (+GA)
    __shared__ float s_wB[64];   // WB1 dots
    __shared__ float s_vB[64];   // WB2 dots
    __shared__ float s_bb[64];   // bB1+bB2

    const int c    = blockIdx.x;
    const int tid  = threadIdx.x;
    const int lane = tid & 31;
    const int rs   = tid >> 1;      // 0..191
    const int half = tid & 1;
    const int mat  = rs >> 6;       // 0:WA2 1:WB1 2:WB2
    const int r    = rs & 63;
    const int grow = ((r >> 4) << 7) + (c << 4) + (r & 15);

    // ---- weights as packed f32x2 ----
    const float* Wp = (mat == 0) ? WA2 : (mat == 1) ? WB1 : WB2;
    u64 wv[32];
    {
        const ulonglong2* wg = (const ulonglong2*)(Wp + (size_t)grow * 128 + half * 64);
#pragma unroll
        for (int k = 0; k < 16; k++) { ulonglong2 q = wg[k]; wv[2*k] = q.x; wv[2*k+1] = q.y; }
    }

    // ---- init SMEM ----
    if (tid < 64) {
        const int gr = ((tid >> 4) << 7) + (c << 4) + (tid & 15);
        s_bb[tid] = bB1[gr] + bB2[gr];
    }
    if (tid < HN) {
        const int g = tid >> 4, i = tid & 15;
        s_in[0][g * 32 + i]      = hA0[tid];   // hA(-1), read at tick 0
        s_in[0][g * 32 + 16 + i] = 0.f;        // hB dots discarded at tick 0
        // s_in[1] fully written by tick 0's broadcast (hA(0) + hB(-1))
    }
    const bool isA = (tid < 16);
    const bool isB = (tid >= 32 && tid < 48);
    float cAr = 0.f, cBr = 0.f, hB_init = 0.f;
    if (isA) cAr = cA0[(c << 4) + tid];
    if (isB) { cBr = cB0[(c << 4) + (tid - 32)]; hB_init = hB0[(c << 4) + (tid - 32)]; }

    // ---- broadcast lanes (tid<64): one v4 store each ----
    uint32_t rdst[2];   // [buffer] remote dst for my (rank, chunk)
    if (tid < 64) {
        const int rk = tid >> 3;       // target rank
        const int q  = tid & 7;        // 16B chunk of the 32-value stage
#pragma unroll
        for (int buf = 0; buf < 2; buf++)
            rdst[buf] = mapa_u32(smem_u32(&s_in[buf][c * 32 + 4 * q]), rk);
    }
    __syncthreads();
    CLUSTER_SYNC_();   // all CTAs initialized before any remote store

    // ---- GA prefetch, distance 2 (mat==0 half==0 lanes) ----
    const bool is_ga = (mat == 0) && (half == 0);
    float ga0 = 0.f, ga1 = 0.f;
    if (is_ga) {
        ga0 = g_GA[grow];
        ga1 = __ldg(&g_GA[(size_t)G4 + grow]);
    }

    const size_t OH = (size_t)SEQN * HN;   // state offset in d_out

    for (int t = 0; t <= SEQN; t++) {
        const int pb = t & 1;

        float ga2 = 0.f;
        if (is_ga && t + 2 < SEQN)
            ga2 = __ldg(&g_GA[(size_t)(t + 2) * G4 + grow]);

        // ===== merged matvec (FFMA2) over grouped s_in layout =====
        {
            const float* hb = s_in[pb] + ((mat == 2) ? 16 : 0);
            u64 a0 = 0ULL, a1 = 0ULL;
#pragma unroll
            for (int gi = 0; gi < 4; gi++) {
                const ulonglong2* hv =
                    (const ulonglong2*)(hb + (4 * half + gi) * 32);
#pragma unroll
                for (int j = 0; j < 4; j++) {
                    ulonglong2 h2 = hv[j];
                    FMA2(a0, wv[gi * 8 + 2 * j],     h2.x);
                    FMA2(a1, wv[gi * 8 + 2 * j + 1], h2.y);
                }
            }
            float2 f0 = *(float2*)&a0, f1 = *(float2*)&a1;
            float s = (f0.x + f0.y) + (f1.x + f1.y);
            s += __shfl_down_sync(0xffffffffu, s, 1);
            if (half == 0) {
                if (mat == 0)      s_uA[r] = s + ga0;
                else if (mat == 1) s_wB[r] = s;
                else               s_vB[r] = s;
            }
        }
        __syncthreads();

        // ===== activations stage h locally; regs kept for GMEM writes =====
        float hA_val = 0.f, cnA = 0.f;
        float hB_val = 0.f, cnB = 0.f;
        if (isA && t < SEQN) {
            const float gi = s_uA[tid];
            const float gf = s_uA[16 + tid];
            const float gg = s_uA[32 + tid];
            const float go = s_uA[48 + tid];
            cnA = sigmfast(gf) * cAr + sigmfast(gi) * tanhfast(gg);
            cAr = cnA;
            hA_val = sigmfast(go) * tanhfast(cnA);
            s_stage[tid] = hA_val;
        }
        if (isB) {
            const int ln = tid - 32;
            if (t == 0) {
                hB_val = hB_init;
                cnB = cBr;
            } else {
                const float gi = s_wB[ln]      + s_vB[ln]      + s_bb[ln];
                const float gf = s_wB[16 + ln] + s_vB[16 + ln] + s_bb[16 + ln];
                const float gg = s_wB[32 + ln] + s_vB[32 + ln] + s_bb[32 + ln];
                const float go = s_wB[48 + ln] + s_vB[48 + ln] + s_bb[48 + ln];
                cnB = sigmfast(gf) * cBr + sigmfast(gi) * tanhfast(gg);
                cBr = cnB;
                hB_val = sigmfast(go) * tanhfast(cnB);
            }
            if (t < SEQN) s_stage[16 + ln] = hB_val;
        }

        // ===== vectorized broadcast: 64 lanes, ONE 16B remote store each =====
        if (t < SEQN && tid < 64) {
            asm volatile("bar.sync 1, 64;" ::: "memory");
            const float4 v = *(const float4*)&s_stage[4 * (tid & 7)];
            st_cluster_v4(rdst[pb ^ 1], v);
        }

        CLUSTER_ARRIVE_();

        // ===== GMEM side-effects + GA rotate (hidden before wait) =====
        if (isB && t >= 1) {
            const int j = (c << 4) + (tid - 32);
            g_HB[(size_t)(t - 1) * HN + j] = hB_val;
            if (write_states && t == SEQN) {
                out[OH + 2 * HN + j] = hB_val;
                out[OH + 3 * HN + j] = cnB;
            }
        }
        if (isA && write_states && t == SEQN - 1) {
            const int j = (c << 4) + tid;
            out[OH + j]      = hA_val;
            out[OH + HN + j] = cnA;
        }
        if (is_ga) { ga0 = ga1; ga1 = ga2; }

        CLUSTER_WAIT_();
    }
}

// ---------------------------------------------------------------------------
// Kernel 3: logits[t] = hB[t] @ Wfc^T + bfc
// ---------------------------------------------------------------------------
__global__ void __launch_bounds__(128) fc_kernel(const float* __restrict__ W,
                                                 const float* __restrict__ b,
                                                 float* __restrict__ out) {
    __shared__ float hs[64 * 128];
    const int tid = threadIdx.x;

    float4 w[32];
    const float4* wg = (const float4*)(W + (size_t)tid * 128);
#pragma unroll
    for (int k = 0; k < 32; k++) w[k] = wg[k];
    const float bias = b[tid];

    const int t0 = blockIdx.x * 64;
    const float4* hg = (const float4*)(g_HB + (size_t)t0 * 128);
    float4* hs4 = (float4*)hs;
#pragma unroll
    for (int i = 0; i < 16; i++) hs4[tid + (i << 7)] = hg[tid + (i << 7)];
    __syncthreads();

    for (int tt = 0; tt < 64; tt++) {
        const float4* hx = (const float4*)(hs + tt * 128);
        float a0 = 0.f, a1 = 0.f, a2 = 0.f, a3 = 0.f;
#pragma unroll
        for (int k = 0; k < 32; k++) {
            float4 h = hx[k];
            a0 = fmaf(w[k].x, h.x, a0);
            a1 = fmaf(w[k].y, h.y, a1);
            a2 = fmaf(w[k].z, h.z, a2);
            a3 = fmaf(w[k].w, h.w, a3);
        }
        out[(size_t)(t0 + tt) * 128 + tid] = (a0 + a1) + (a2 + a3) + bias;
    }
}

// ---------------------------------------------------------------------------
// launch
// inputs: 0 x, 1 hA, 2 cA, 3 hB, 4 cB, 5 WA1, 6 bA1, 7 WA2, 8 bA2,
//         9 WB1, 10 bB1, 11 WB2, 12 bB2, 13 Wfc, 14 bfc
// ---------------------------------------------------------------------------
extern "C" void kernel_launch(void* const* d_in, const int* in_sizes, int n_in,
                              void* d_out, int out_size) {
    const float* x   = (const float*)d_in[0];
    const float* hA0 = (const float*)d_in[1];
    const float* cA0 = (const float*)d_in[2];
    const float* hB0 = (const float*)d_in[3];
    const float* cB0 = (const float*)d_in[4];
    const float* WA1 = (const float*)d_in[5];
    const float* bA1 = (const float*)d_in[6];
    const float* WA2 = (const float*)d_in[7];
    const float* bA2 = (const float*)d_in[8];
    const float* WB1 = (const float*)d_in[9];
    const float* bB1 = (const float*)d_in[10];
    const float* WB2 = (const float*)d_in[11];
    const float* bB2 = (const float*)d_in[12];
    const float* Wfc = (const float*)d_in[13];
    const float* bfc = (const float*)d_in[14];
    float* out = (float*)d_out;

    const int write_states = (out_size >= SEQN * HN + 4 * HN) ? 1 : 0;

    ga_kernel<<<dim3(SEQN / 64, 4), 128>>>(x, WA1, bA1, bA2);
    recur_kernel<<<8, 384>>>(WA2, WB1, WB2, bB1, bB2, hA0, cA0, hB0, cB0, out,
                             write_states);
    fc_kernel<<<SEQN / 64, 128>>>(Wfc, bfc, out);
}

// round 12
// speedup vs baseline: 1.4598x; 1.1339x over previous
#include <cuda_runtime.h>
#include <cstdint>

#define SEQN 65536
#define HN   128
#define G4   512   // 4*H

typedef unsigned long long u64;

// Scratch (device globals: allocation-free per harness rules)
__device__ float g_GA[(size_t)SEQN * G4];   // precomputed x@WA1^T + bA1 + bA2
__device__ float g_HB[(size_t)SEQN * HN];   // hB per step, consumed by fc GEMM

// ---------------------------------------------------------------------------
// helpers
// ---------------------------------------------------------------------------
__device__ __forceinline__ float tanhfast(float x) {
    float y;
    asm("tanh.approx.f32 %0, %1;" : "=f"(y) : "f"(x));
    return y;
}
__device__ __forceinline__ float sigmfast(float x) {
    return fmaf(tanhfast(0.5f * x), 0.5f, 0.5f);
}

__device__ __forceinline__ uint32_t smem_u32(const void* p) {
    return (uint32_t)__cvta_generic_to_shared(p);
}
__device__ __forceinline__ uint32_t mapa_u32(uint32_t a, int rank) {
    uint32_t r;
    asm("mapa.shared::cluster.u32 %0, %1, %2;" : "=r"(r) : "r"(a), "r"(rank));
    return r;
}

// one 16-byte vector store into a peer CTA's SMEM
__device__ __forceinline__ void st_cluster_v4(uint32_t addr, float4 v) {
    asm volatile("st.shared::cluster.v4.f32 [%0], {%1, %2, %3, %4};"
                 :: "r"(addr), "f"(v.x), "f"(v.y), "f"(v.z), "f"(v.w) : "memory");
}

#define FMA2(acc, w, h) \
    asm("fma.rn.f32x2 %0, %1, %2, %0;" : "+l"(acc) : "l"(w), "l"(h))

#define CLUSTER_ARRIVE_() asm volatile("barrier.cluster.arrive.aligned;" ::: "memory")
#define CLUSTER_WAIT_()   asm volatile("barrier.cluster.wait.aligned;"   ::: "memory")
#define CLUSTER_SYNC_()   do { CLUSTER_ARRIVE_(); CLUSTER_WAIT_(); } while (0)

// ---------------------------------------------------------------------------
// Kernel 1: GA[t, 512] = x[t] @ WA1^T + bA1 + bA2
// ---------------------------------------------------------------------------
__global__ void __launch_bounds__(128) ga_kernel(const float* __restrict__ x,
                                                 const float* __restrict__ W,
                                                 const float* __restrict__ b1,
                                                 const float* __restrict__ b2) {
    __shared__ float xs[64 * 128];
    const int tid = threadIdx.x;
    const int row = (blockIdx.y << 7) + tid;

    float4 w[32];
    const float4* wg = (const float4*)(W + (size_t)row * 128);
#pragma unroll
    for (int k = 0; k < 32; k++) w[k] = wg[k];
    const float bias = b1[row] + b2[row];

    const int t0 = blockIdx.x * 64;
    const float4* xg = (const float4*)(x + (size_t)t0 * 128);
    float4* xs4 = (float4*)xs;
#pragma unroll
    for (int i = 0; i < 16; i++) xs4[tid + (i << 7)] = xg[tid + (i << 7)];
    __syncthreads();

    for (int tt = 0; tt < 64; tt++) {
        const float4* hx = (const float4*)(xs + tt * 128);
        float a0 = 0.f, a1 = 0.f, a2 = 0.f, a3 = 0.f;
#pragma unroll
        for (int k = 0; k < 32; k++) {
            float4 h = hx[k];
            a0 = fmaf(w[k].x, h.x, a0);
            a1 = fmaf(w[k].y, h.y, a1);
            a2 = fmaf(w[k].z, h.z, a2);
            a3 = fmaf(w[k].w, h.w, a3);
        }
        g_GA[(size_t)(t0 + tt) * G4 + row] = (a0 + a1) + (a2 + a3) + bias;
    }
}

// ---------------------------------------------------------------------------
// Kernel 2: R11 champion, slimmed to 192 threads / 6 warps.
// Thread tid owns ONE full 128-wide weight row: mat = tid>>6 (0:WA2 1:WB1
// 2:WB2), r = tid&63, 64 FFMA2 into 4 accumulators, dot written directly
// (no shuffle, no half-merge). Acts: warp0 lanes 0-15 = cell A, warp1 lanes
// 0-15 = cell B. Broadcast: 64 lanes (warps 0-1), one st.shared::cluster.v4
// each. One barrier.cluster per tick; GMEM side-writes + GA rotate hidden
// between arrive and wait. Incoming buffer grouped by source rank.
// ---------------------------------------------------------------------------
__global__ void __cluster_dims__(8, 1, 1) __launch_bounds__(192, 1)
recur_kernel(const float* __restrict__ WA2, const float* __restrict__ WB1,
             const float* __restrict__ WB2, const float* __restrict__ bB1,
             const float* __restrict__ bB2, const float* __restrict__ hA0,
             const float* __restrict__ cA0, const float* __restrict__ hB0,
             const float* __restrict__ cB0, float* __restrict__ out,
             int write_states) {
    __shared__ alignas(16) float s_in[2][256];   // grouped: rank g -> [32g..32g+32)
    __shared__ alignas(16) float s_stage[32];    // {16 hA, 16 hB} outgoing
    __shared__ float s_uA[64];   // WA2 dots (+GA)
    __shared__ float s_wB[64];   // WB1 dots
    __shared__ float s_vB[64];   // WB2 dots
    __shared__ float s_bb[64];   // bB1+bB2

    const int c    = blockIdx.x;
    const int tid  = threadIdx.x;
    const int lane = tid & 31;
    const int mat  = tid >> 6;      // 0:WA2 1:WB1 2:WB2
    const int r    = tid & 63;      // row within matrix slice
    const int grow = ((r >> 4) << 7) + (c << 4) + (r & 15);

    // ---- weights: one full row (128 floats) as 64 packed f32x2 ----
    const float* Wp = (mat == 0) ? WA2 : (mat == 1) ? WB1 : WB2;
    u64 wv[64];
    {
        const ulonglong2* wg = (const ulonglong2*)(Wp + (size_t)grow * 128);
#pragma unroll
        for (int k = 0; k < 32; k++) { ulonglong2 q = wg[k]; wv[2*k] = q.x; wv[2*k+1] = q.y; }
    }

    // ---- init SMEM ----
    if (tid < 64) {
        const int gr = ((tid >> 4) << 7) + (c << 4) + (tid & 15);
        s_bb[tid] = bB1[gr] + bB2[gr];
    }
    if (tid < HN) {
        const int g = tid >> 4, i = tid & 15;
        s_in[0][g * 32 + i]      = hA0[tid];   // hA(-1), read at tick 0
        s_in[0][g * 32 + 16 + i] = 0.f;        // hB dots discarded at tick 0
        // s_in[1] fully written by tick 0's broadcast (hA(0) + hB(-1))
    }
    const bool isA = (tid < 16);
    const bool isB = (tid >= 32 && tid < 48);
    float cAr = 0.f, cBr = 0.f, hB_init = 0.f;
    if (isA) cAr = cA0[(c << 4) + tid];
    if (isB) { cBr = cB0[(c << 4) + (tid - 32)]; hB_init = hB0[(c << 4) + (tid - 32)]; }

    // ---- broadcast lanes (tid<64): one v4 store each ----
    uint32_t rdst[2];   // [buffer] remote dst for my (rank, chunk)
    if (tid < 64) {
        const int rk = tid >> 3;       // target rank
        const int q  = tid & 7;        // 16B chunk of the 32-value stage
#pragma unroll
        for (int buf = 0; buf < 2; buf++)
            rdst[buf] = mapa_u32(smem_u32(&s_in[buf][c * 32 + 4 * q]), rk);
    }
    __syncthreads();
    CLUSTER_SYNC_();   // all CTAs initialized before any remote store

    // ---- GA prefetch, distance 2 (mat==0 lanes = one per WA2 row) ----
    const bool is_ga = (mat == 0);
    float ga0 = 0.f, ga1 = 0.f;
    if (is_ga) {
        ga0 = g_GA[grow];
        ga1 = __ldg(&g_GA[(size_t)G4 + grow]);
    }

    const size_t OH = (size_t)SEQN * HN;   // state offset in d_out

    for (int t = 0; t <= SEQN; t++) {
        const int pb = t & 1;

        float ga2 = 0.f;
        if (is_ga && t + 2 < SEQN)
            ga2 = __ldg(&g_GA[(size_t)(t + 2) * G4 + grow]);

        // ===== full-row matvec (FFMA2, 4 accumulators) =====
        {
            const float* hb = s_in[pb] + ((mat == 2) ? 16 : 0);
            u64 a0 = 0ULL, a1 = 0ULL, a2 = 0ULL, a3 = 0ULL;
#pragma unroll
            for (int g = 0; g < 8; g++) {
                const ulonglong2* hv = (const ulonglong2*)(hb + g * 32);
                ulonglong2 h01 = hv[0];
                ulonglong2 h23 = hv[1];
                FMA2(a0, wv[g * 8 + 0], h01.x);
                FMA2(a1, wv[g * 8 + 1], h01.y);
                FMA2(a2, wv[g * 8 + 2], h23.x);
                FMA2(a3, wv[g * 8 + 3], h23.y);
                ulonglong2 h45 = hv[2];
                ulonglong2 h67 = hv[3];
                FMA2(a0, wv[g * 8 + 4], h45.x);
                FMA2(a1, wv[g * 8 + 5], h45.y);
                FMA2(a2, wv[g * 8 + 6], h67.x);
                FMA2(a3, wv[g * 8 + 7], h67.y);
            }
            float2 f0 = *(float2*)&a0, f1 = *(float2*)&a1;
            float2 f2 = *(float2*)&a2, f3 = *(float2*)&a3;
            const float s = ((f0.x + f0.y) + (f1.x + f1.y)) +
                            ((f2.x + f2.y) + (f3.x + f3.y));
            if (mat == 0)      s_uA[r] = s + ga0;
            else if (mat == 1) s_wB[r] = s;
            else               s_vB[r] = s;
        }
        __syncthreads();

        // ===== activations stage h locally; regs kept for GMEM writes =====
        float hA_val = 0.f, cnA = 0.f;
        float hB_val = 0.f, cnB = 0.f;
        if (isA && t < SEQN) {
            const float gi = s_uA[tid];
            const float gf = s_uA[16 + tid];
            const float gg = s_uA[32 + tid];
            const float go = s_uA[48 + tid];
            cnA = sigmfast(gf) * cAr + sigmfast(gi) * tanhfast(gg);
            cAr = cnA;
            hA_val = sigmfast(go) * tanhfast(cnA);
            s_stage[tid] = hA_val;
        }
        if (isB) {
            const int ln = tid - 32;
            if (t == 0) {
                hB_val = hB_init;
                cnB = cBr;
            } else {
                const float gi = s_wB[ln]      + s_vB[ln]      + s_bb[ln];
                const float gf = s_wB[16 + ln] + s_vB[16 + ln] + s_bb[16 + ln];
                const float gg = s_wB[32 + ln] + s_vB[32 + ln] + s_bb[32 + ln];
                const float go = s_wB[48 + ln] + s_vB[48 + ln] + s_bb[48 + ln];
                cnB = sigmfast(gf) * cBr + sigmfast(gi) * tanhfast(gg);
                cBr = cnB;
                hB_val = sigmfast(go) * tanhfast(cnB);
            }
            if (t < SEQN) s_stage[16 + ln] = hB_val;
        }

        // ===== vectorized broadcast: 64 lanes, ONE 16B remote store each =====
        if (t < SEQN && tid < 64) {
            asm volatile("bar.sync 1, 64;" ::: "memory");
            const float4 v = *(const float4*)&s_stage[4 * (tid & 7)];
            st_cluster_v4(rdst[pb ^ 1], v);
        }

        CLUSTER_ARRIVE_();

        // ===== GMEM side-effects + GA rotate (hidden before wait) =====
        if (isB && t >= 1) {
            const int j = (c << 4) + (tid - 32);
            g_HB[(size_t)(t - 1) * HN + j] = hB_val;
            if (write_states && t == SEQN) {
                out[OH + 2 * HN + j] = hB_val;
                out[OH + 3 * HN + j] = cnB;
            }
        }
        if (isA && write_states && t == SEQN - 1) {
            const int j = (c << 4) + tid;
            out[OH + j]      = hA_val;
            out[OH + HN + j] = cnA;
        }
        if (is_ga) { ga0 = ga1; ga1 = ga2; }

        CLUSTER_WAIT_();
    }
}

// ---------------------------------------------------------------------------
// Kernel 3: logits[t] = hB[t] @ Wfc^T + bfc
// ---------------------------------------------------------------------------
__global__ void __launch_bounds__(128) fc_kernel(const float* __restrict__ W,
                                                 const float* __restrict__ b,
                                                 float* __restrict__ out) {
    __shared__ float hs[64 * 128];
    const int tid = threadIdx.x;

    float4 w[32];
    const float4* wg = (const float4*)(W + (size_t)tid * 128);
#pragma unroll
    for (int k = 0; k < 32; k++) w[k] = wg[k];
    const float bias = b[tid];

    const int t0 = blockIdx.x * 64;
    const float4* hg = (const float4*)(g_HB + (size_t)t0 * 128);
    float4* hs4 = (float4*)hs;
#pragma unroll
    for (int i = 0; i < 16; i++) hs4[tid + (i << 7)] = hg[tid + (i << 7)];
    __syncthreads();

    for (int tt = 0; tt < 64; tt++) {
        const float4* hx = (const float4*)(hs + tt * 128);
        float a0 = 0.f, a1 = 0.f, a2 = 0.f, a3 = 0.f;
#pragma unroll
        for (int k = 0; k < 32; k++) {
            float4 h = hx[k];
            a0 = fmaf(w[k].x, h.x, a0);
            a1 = fmaf(w[k].y, h.y, a1);
            a2 = fmaf(w[k].z, h.z, a2);
            a3 = fmaf(w[k].w, h.w, a3);
        }
        out[(size_t)(t0 + tt) * 128 + tid] = (a0 + a1) + (a2 + a3) + bias;
    }
}

// ---------------------------------------------------------------------------
// launch
// inputs: 0 x, 1 hA, 2 cA, 3 hB, 4 cB, 5 WA1, 6 bA1, 7 WA2, 8 bA2,
//         9 WB1, 10 bB1, 11 WB2, 12 bB2, 13 Wfc, 14 bfc
// ---------------------------------------------------------------------------
extern "C" void kernel_launch(void* const* d_in, const int* in_sizes, int n_in,
                              void* d_out, int out_size) {
    const float* x   = (const float*)d_in[0];
    const float* hA0 = (const float*)d_in[1];
    const float* cA0 = (const float*)d_in[2];
    const float* hB0 = (const float*)d_in[3];
    const float* cB0 = (const float*)d_in[4];
    const float* WA1 = (const float*)d_in[5];
    const float* bA1 = (const float*)d_in[6];
    const float* WA2 = (const float*)d_in[7];
    const float* bA2 = (const float*)d_in[8];
    const float* WB1 = (const float*)d_in[9];
    const float* bB1 = (const float*)d_in[10];
    const float* WB2 = (const float*)d_in[11];
    const float* bB2 = (const float*)d_in[12];
    const float* Wfc = (const float*)d_in[13];
    const float* bfc = (const float*)d_in[14];
    float* out = (float*)d_out;

    const int write_states = (out_size >= SEQN * HN + 4 * HN) ? 1 : 0;

    ga_kernel<<<dim3(SEQN / 64, 4), 128>>>(x, WA1, bA1, bA2);
    recur_kernel<<<8, 192>>>(WA2, WB1, WB2, bB1, bB2, hA0, cA0, hB0, cB0, out,
                             write_states);
    fc_kernel<<<SEQN / 64, 128>>>(Wfc, bfc, out);
}

// round 13
// speedup vs baseline: 1.5644x; 1.0716x over previous
#include <cuda_runtime.h>
#include <cstdint>

#define SEQN 65536
#define HN   128
#define G4   512   // 4*H

typedef unsigned long long u64;

// Scratch (device globals: allocation-free per harness rules)
__device__ float g_GA[(size_t)SEQN * G4];   // precomputed x@WA1^T + bA1 + bA2
__device__ float g_HB[(size_t)SEQN * HN];   // hB per step, consumed by fc GEMM

// ---------------------------------------------------------------------------
// helpers
// ---------------------------------------------------------------------------
__device__ __forceinline__ float tanhfast(float x) {
    float y;
    asm("tanh.approx.f32 %0, %1;" : "=f"(y) : "f"(x));
    return y;
}
__device__ __forceinline__ float sigmfast(float x) {
    return fmaf(tanhfast(0.5f * x), 0.5f, 0.5f);
}

__device__ __forceinline__ uint32_t smem_u32(const void* p) {
    return (uint32_t)__cvta_generic_to_shared(p);
}
__device__ __forceinline__ uint32_t mapa_u32(uint32_t a, int rank) {
    uint32_t r;
    asm("mapa.shared::cluster.u32 %0, %1, %2;" : "=r"(r) : "r"(a), "r"(rank));
    return r;
}

// one 16-byte vector store into a peer CTA's SMEM
__device__ __forceinline__ void st_cluster_v4(uint32_t addr, float4 v) {
    asm volatile("st.shared::cluster.v4.f32 [%0], {%1, %2, %3, %4};"
                 :: "r"(addr), "f"(v.x), "f"(v.y), "f"(v.z), "f"(v.w) : "memory");
}

#define FMA2(acc, w, h) \
    asm("fma.rn.f32x2 %0, %1, %2, %0;" : "+l"(acc) : "l"(w), "l"(h))

#define CLUSTER_ARRIVE_() asm volatile("barrier.cluster.arrive.aligned;" ::: "memory")
#define CLUSTER_WAIT_()   asm volatile("barrier.cluster.wait.aligned;"   ::: "memory")
#define CLUSTER_SYNC_()   do { CLUSTER_ARRIVE_(); CLUSTER_WAIT_(); } while (0)

// ---------------------------------------------------------------------------
// Kernel 1: GA[t, 512] = x[t] @ WA1^T + bA1 + bA2
// ---------------------------------------------------------------------------
__global__ void __launch_bounds__(128) ga_kernel(const float* __restrict__ x,
                                                 const float* __restrict__ W,
                                                 const float* __restrict__ b1,
                                                 const float* __restrict__ b2) {
    __shared__ float xs[64 * 128];
    const int tid = threadIdx.x;
    const int row = (blockIdx.y << 7) + tid;

    float4 w[32];
    const float4* wg = (const float4*)(W + (size_t)row * 128);
#pragma unroll
    for (int k = 0; k < 32; k++) w[k] = wg[k];
    const float bias = b1[row] + b2[row];

    const int t0 = blockIdx.x * 64;
    const float4* xg = (const float4*)(x + (size_t)t0 * 128);
    float4* xs4 = (float4*)xs;
#pragma unroll
    for (int i = 0; i < 16; i++) xs4[tid + (i << 7)] = xg[tid + (i << 7)];
    __syncthreads();

    for (int tt = 0; tt < 64; tt++) {
        const float4* hx = (const float4*)(xs + tt * 128);
        float a0 = 0.f, a1 = 0.f, a2 = 0.f, a3 = 0.f;
#pragma unroll
        for (int k = 0; k < 32; k++) {
            float4 h = hx[k];
            a0 = fmaf(w[k].x, h.x, a0);
            a1 = fmaf(w[k].y, h.y, a1);
            a2 = fmaf(w[k].z, h.z, a2);
            a3 = fmaf(w[k].w, h.w, a3);
        }
        g_GA[(size_t)(t0 + tt) * G4 + row] = (a0 + a1) + (a2 + a3) + bias;
    }
}

// ---------------------------------------------------------------------------
// Kernel 2: 128 threads / 4 warps — one warp per SMSP, balanced issue.
// Thread tid: FULL row r = tid>>1 of (WA2 if even tid else WB1) +
//             HALF row r of WB2 (half = tid&1). vB merged via shfl.down(1).
// Incoming s_in grouped by source rank: [32g..32g+16) hA, [+16..+32) hB.
// Acts: warp0 lanes0-15 = cell A(t), warp1 lanes0-15 = cell B(t-1); each act
// warp stages 16 floats, __syncwarp, then its 32 lanes broadcast 4 v4 chunks
// x 8 ranks (A-drain overlaps act B; no cross-warp staging barrier).
// One barrier.cluster per tick; GMEM + GA rotate hidden between arrive/wait.
// ---------------------------------------------------------------------------
__global__ void __cluster_dims__(8, 1, 1) __launch_bounds__(128, 1)
recur_kernel(const float* __restrict__ WA2, const float* __restrict__ WB1,
             const float* __restrict__ WB2, const float* __restrict__ bB1,
             const float* __restrict__ bB2, const float* __restrict__ hA0,
             const float* __restrict__ cA0, const float* __restrict__ hB0,
             const float* __restrict__ cB0, float* __restrict__ out,
             int write_states) {
    __shared__ alignas(16) float s_in[2][256];   // grouped: rank g -> [32g..32g+32)
    __shared__ alignas(16) float s_stA[16];      // outgoing hA
    __shared__ alignas(16) float s_stB[16];      // outgoing hB
    __shared__ float s_uA[64];   // WA2 dots (+GA)
    __shared__ float s_wB[64];   // WB1 dots
    __shared__ float s_vB[64];   // WB2 dots
    __shared__ float s_bb[64];   // bB1+bB2

    const int c    = blockIdx.x;
    const int tid  = threadIdx.x;
    const int lane = tid & 31;
    const int r    = tid >> 1;      // row 0..63 within each matrix slice
    const int ho   = tid & 1;       // 0: WA2 full row, 1: WB1 full row; WB2 half
    const int grow = ((r >> 4) << 7) + (c << 4) + (r & 15);

    // ---- full row (WA2 or WB1): 64 packed f32x2 ----
    const float* Wf = ho ? WB1 : WA2;
    u64 wf[64];
    {
        const ulonglong2* wg = (const ulonglong2*)(Wf + (size_t)grow * 128);
#pragma unroll
        for (int k = 0; k < 32; k++) { ulonglong2 q = wg[k]; wf[2*k] = q.x; wf[2*k+1] = q.y; }
    }
    // ---- half row of WB2: 32 packed f32x2 ----
    u64 wh[32];
    {
        const ulonglong2* wg = (const ulonglong2*)(WB2 + (size_t)grow * 128 + ho * 64);
#pragma unroll
        for (int k = 0; k < 16; k++) { ulonglong2 q = wg[k]; wh[2*k] = q.x; wh[2*k+1] = q.y; }
    }

    // ---- init SMEM ----
    if (tid < 64) {
        const int gr = ((tid >> 4) << 7) + (c << 4) + (tid & 15);
        s_bb[tid] = bB1[gr] + bB2[gr];
    }
    if (tid < HN) {
        const int g = tid >> 4, i = tid & 15;
        s_in[0][g * 32 + i]      = hA0[tid];   // hA(-1), read at tick 0
        s_in[0][g * 32 + 16 + i] = 0.f;        // hB dots discarded at tick 0
    }
    const bool isA = (tid < 16);                 // warp 0 act lanes
    const bool isB = (tid >= 32 && tid < 48);    // warp 1 act lanes
    float cAr = 0.f, cBr = 0.f, hB_init = 0.f;
    if (isA) cAr = cA0[(c << 4) + tid];
    if (isB) { cBr = cB0[(c << 4) + (tid - 32)]; hB_init = hB0[(c << 4) + (tid - 32)]; }

    // ---- broadcast addresses: warp0 lanes -> A chunks, warp1 lanes -> B ----
    uint32_t rdst[2];   // [buffer]
    if (tid < 64) {
        const int rk = lane >> 2;          // target rank (0..7)
        const int q  = lane & 3;           // 16B chunk (0..3)
        const int off = (tid < 32) ? 0 : 16;   // A half vs B half of my group
#pragma unroll
        for (int buf = 0; buf < 2; buf++)
            rdst[buf] = mapa_u32(smem_u32(&s_in[buf][c * 32 + off + 4 * q]), rk);
    }
    __syncthreads();
    CLUSTER_SYNC_();   // all CTAs initialized before any remote store

    // ---- GA prefetch, distance 2 (even tids own WA2 rows) ----
    const bool is_ga = (ho == 0);
    float ga0 = 0.f, ga1 = 0.f;
    if (is_ga) {
        ga0 = g_GA[grow];
        ga1 = __ldg(&g_GA[(size_t)G4 + grow]);
    }

    const size_t OH = (size_t)SEQN * HN;   // state offset in d_out

    for (int t = 0; t <= SEQN; t++) {
        const int pb = t & 1;

        float ga2 = 0.f;
        if (is_ga && t + 2 < SEQN)
            ga2 = __ldg(&g_GA[(size_t)(t + 2) * G4 + grow]);

        // ===== matvec: full row (hA) + half WB2 row (hB), FFMA2 =====
        {
            const float* base = s_in[pb];
            u64 a0 = 0ULL, a1 = 0ULL, a2 = 0ULL, a3 = 0ULL;   // full row
            u64 b0 = 0ULL, b1 = 0ULL;                          // half row
#pragma unroll
            for (int g = 0; g < 8; g++) {
                const ulonglong2* hv = (const ulonglong2*)(base + 32 * g);
                ulonglong2 h01 = hv[0];
                ulonglong2 h23 = hv[1];
                FMA2(a0, wf[g * 8 + 0], h01.x);
                FMA2(a1, wf[g * 8 + 1], h01.y);
                FMA2(a2, wf[g * 8 + 2], h23.x);
                FMA2(a3, wf[g * 8 + 3], h23.y);
                FMA2(a0, wf[g * 8 + 4], hv[2].x);
                FMA2(a1, wf[g * 8 + 5], hv[2].y);
                FMA2(a2, wf[g * 8 + 6], hv[3].x);
                FMA2(a3, wf[g * 8 + 7], hv[3].y);
            }
#pragma unroll
            for (int g = 0; g < 4; g++) {
                // hB groups for my half: groups [4*ho .. 4*ho+4)
                const ulonglong2* hv =
                    (const ulonglong2*)(base + 32 * (4 * ho + g) + 16);
                ulonglong2 h01 = hv[0];
                ulonglong2 h23 = hv[1];
                FMA2(b0, wh[g * 8 + 0], h01.x);
                FMA2(b1, wh[g * 8 + 1], h01.y);
                FMA2(b0, wh[g * 8 + 2], h23.x);
                FMA2(b1, wh[g * 8 + 3], h23.y);
                FMA2(b0, wh[g * 8 + 4], hv[2].x);
                FMA2(b1, wh[g * 8 + 5], hv[2].y);
                FMA2(b0, wh[g * 8 + 6], hv[3].x);
                FMA2(b1, wh[g * 8 + 7], hv[3].y);
            }
            float2 f0 = *(float2*)&a0, f1 = *(float2*)&a1;
            float2 f2 = *(float2*)&a2, f3 = *(float2*)&a3;
            const float sf = ((f0.x + f0.y) + (f1.x + f1.y)) +
                             ((f2.x + f2.y) + (f3.x + f3.y));
            float2 g0 = *(float2*)&b0, g1 = *(float2*)&b1;
            float sh = (g0.x + g0.y) + (g1.x + g1.y);
            sh += __shfl_down_sync(0xffffffffu, sh, 1);   // merge WB2 halves
            if (ho == 0) {
                s_uA[r] = sf + ga0;
                s_vB[r] = sh;
            } else {
                s_wB[r] = sf;
            }
        }
        __syncthreads();

        // ===== warp 0: act A (step t) + A broadcast =====
        float hA_val = 0.f, cnA = 0.f;
        float hB_val = 0.f, cnB = 0.f;
        if (tid < 32) {
            if (isA && t < SEQN) {
                const float gi = s_uA[tid];
                const float gf = s_uA[16 + tid];
                const float gg = s_uA[32 + tid];
                const float go = s_uA[48 + tid];
                cnA = sigmfast(gf) * cAr + sigmfast(gi) * tanhfast(gg);
                cAr = cnA;
                hA_val = sigmfast(go) * tanhfast(cnA);
                s_stA[tid] = hA_val;
            }
            __syncwarp();
            if (t < SEQN) {
                const float4 v = *(const float4*)&s_stA[4 * (lane & 3)];
                st_cluster_v4(rdst[pb ^ 1], v);
            }
        }

        // ===== warp 1: act B (step t-1) + B broadcast =====
        if (tid >= 32 && tid < 64) {
            if (isB) {
                const int ln = tid - 32;
                if (t == 0) {
                    hB_val = hB_init;
                    cnB = cBr;
                } else {
                    const float gi = s_wB[ln]      + s_vB[ln]      + s_bb[ln];
                    const float gf = s_wB[16 + ln] + s_vB[16 + ln] + s_bb[16 + ln];
                    const float gg = s_wB[32 + ln] + s_vB[32 + ln] + s_bb[32 + ln];
                    const float go = s_wB[48 + ln] + s_vB[48 + ln] + s_bb[48 + ln];
                    cnB = sigmfast(gf) * cBr + sigmfast(gi) * tanhfast(gg);
                    cBr = cnB;
                    hB_val = sigmfast(go) * tanhfast(cnB);
                }
                s_stB[tid - 32] = hB_val;
            }
            __syncwarp();
            if (t < SEQN) {
                const float4 v = *(const float4*)&s_stB[4 * (lane & 3)];
                st_cluster_v4(rdst[pb ^ 1], v);
            }
        }

        CLUSTER_ARRIVE_();

        // ===== GMEM side-effects + GA rotate (hidden before wait) =====
        if (isB && t >= 1) {
            const int j = (c << 4) + (tid - 32);
            g_HB[(size_t)(t - 1) * HN + j] = hB_val;
            if (write_states && t == SEQN) {
                out[OH + 2 * HN + j] = hB_val;
                out[OH + 3 * HN + j] = cnB;
            }
        }
        if (isA && write_states && t == SEQN - 1) {
            const int j = (c << 4) + tid;
            out[OH + j]      = hA_val;
            out[OH + HN + j] = cnA;
        }
        if (is_ga) { ga0 = ga1; ga1 = ga2; }

        CLUSTER_WAIT_();
    }
}

// ---------------------------------------------------------------------------
// Kernel 3: logits[t] = hB[t] @ Wfc^T + bfc
// ---------------------------------------------------------------------------
__global__ void __launch_bounds__(128) fc_kernel(const float* __restrict__ W,
                                                 const float* __restrict__ b,
                                                 float* __restrict__ out) {
    __shared__ float hs[64 * 128];
    const int tid = threadIdx.x;

    float4 w[32];
    const float4* wg = (const float4*)(W + (size_t)tid * 128);
#pragma unroll
    for (int k = 0; k < 32; k++) w[k] = wg[k];
    const float bias = b[tid];

    const int t0 = blockIdx.x * 64;
    const float4* hg = (const float4*)(g_HB + (size_t)t0 * 128);
    float4* hs4 = (float4*)hs;
#pragma unroll
    for (int i = 0; i < 16; i++) hs4[tid + (i << 7)] = hg[tid + (i << 7)];
    __syncthreads();

    for (int tt = 0; tt < 64; tt++) {
        const float4* hx = (const float4*)(hs + tt * 128);
        float a0 = 0.f, a1 = 0.f, a2 = 0.f, a3 = 0.f;
#pragma unroll
        for (int k = 0; k < 32; k++) {
            float4 h = hx[k];
            a0 = fmaf(w[k].x, h.x, a0);
            a1 = fmaf(w[k].y, h.y, a1);
            a2 = fmaf(w[k].z, h.z, a2);
            a3 = fmaf(w[k].w, h.w, a3);
        }
        out[(size_t)(t0 + tt) * 128 + tid] = (a0 + a1) + (a2 + a3) + bias;
    }
}

// ---------------------------------------------------------------------------
// launch
// inputs: 0 x, 1 hA, 2 cA, 3 hB, 4 cB, 5 WA1, 6 bA1, 7 WA2, 8 bA2,
//         9 WB1, 10 bB1, 11 WB2, 12 bB2, 13 Wfc, 14 bfc
// ---------------------------------------------------------------------------
extern "C" void kernel_launch(void* const* d_in, const int* in_sizes, int n_in,
                              void* d_out, int out_size) {
    const float* x   = (const float*)d_in[0];
    const float* hA0 = (const float*)d_in[1];
    const float* cA0 = (const float*)d_in[2];
    const float* hB0 = (const float*)d_in[3];
    const float* cB0 = (const float*)d_in[4];
    const float* WA1 = (const float*)d_in[5];
    const float* bA1 = (const float*)d_in[6];
    const float* WA2 = (const float*)d_in[7];
    const float* bA2 = (const float*)d_in[8];
    const float* WB1 = (const float*)d_in[9];
    const float* bB1 = (const float*)d_in[10];
    const float* WB2 = (const float*)d_in[11];
    const float* bB2 = (const float*)d_in[12];
    const float* Wfc = (const float*)d_in[13];
    const float* bfc = (const float*)d_in[14];
    float* out = (float*)d_out;

    const int write_states = (out_size >= SEQN * HN + 4 * HN) ? 1 : 0;

    ga_kernel<<<dim3(SEQN / 64, 4), 128>>>(x, WA1, bA1, bA2);
    recur_kernel<<<8, 128>>>(WA2, WB1, WB2, bB1, bB2, hA0, cA0, hB0, cB0, out,
                             write_states);
    fc_kernel<<<SEQN / 64, 128>>>(Wfc, bfc, out);
}